// round 1
// baseline (speedup 1.0000x reference)
#include <cuda_runtime.h>
#include <cuda_bf16.h>
#include <math.h>

// Problem constants
#define Bn   2
#define Sn   2048
#define HSn  2048
#define Hn   16
#define HKVn 4
#define Dn   128
#define Tn   (Bn*Sn)          // 4096 tokens

// -------------------- scratch (device globals; allocation-free) -----------
__device__ float g_q[(size_t)Tn * (Hn*Dn)];     // 4096 x 2048
__device__ float g_k[(size_t)Tn * (HKVn*Dn)];   // 4096 x 512
__device__ float g_v[(size_t)Tn * (HKVn*Dn)];   // 4096 x 512
__device__ float g_ao[(size_t)Tn * (Hn*Dn)];    // 4096 x 2048

// ==================== fp32 NT GEMM: C[M,N] = A[M,K] * B[N,K]^T ============
// 128x128 tile, BK=16, 256 threads, 8x8 per thread.
#define GT 128
#define GBK 16

__global__ __launch_bounds__(256) void gemm_nt(const float* __restrict__ A,
                                               const float* __restrict__ Bw,
                                               float* __restrict__ C,
                                               int M, int N, int K)
{
    __shared__ float As[GBK][GT];
    __shared__ float Bs[GBK][GT];

    const int bx = blockIdx.x;         // N tile
    const int by = blockIdx.y;         // M tile
    const int tid = threadIdx.x;
    const int lane = tid & 31, warp = tid >> 5;
    const int wr = warp >> 1;          // 0..3 (32 rows each)
    const int wc = warp & 1;           // 0..1 (64 cols each)
    const int lr = lane >> 3;          // 0..3
    const int lc = lane & 7;           // 0..7

    const int rbase = wr*32 + lr*8;    // row offset within tile
    const int cbase = wc*64 + lc*8;    // col offset within tile

    float acc[8][8];
    #pragma unroll
    for (int i = 0; i < 8; i++)
        #pragma unroll
        for (int j = 0; j < 8; j++) acc[i][j] = 0.f;

    for (int k0 = 0; k0 < K; k0 += GBK) {
        // cooperative load: 128 rows x 16 cols each for A and B (float4)
        #pragma unroll
        for (int i = 0; i < 2; i++) {
            int id = tid + i*256;            // 0..511
            int r  = id >> 2;                // 0..127
            int c4 = id & 3;                 // 0..3
            float4 va = *(const float4*)(A + (size_t)(by*GT + r)*K + k0 + c4*4);
            As[c4*4+0][r] = va.x; As[c4*4+1][r] = va.y;
            As[c4*4+2][r] = va.z; As[c4*4+3][r] = va.w;
            float4 vb = *(const float4*)(Bw + (size_t)(bx*GT + r)*K + k0 + c4*4);
            Bs[c4*4+0][r] = vb.x; Bs[c4*4+1][r] = vb.y;
            Bs[c4*4+2][r] = vb.z; Bs[c4*4+3][r] = vb.w;
        }
        __syncthreads();

        #pragma unroll
        for (int k = 0; k < GBK; k++) {
            float a[8], b[8];
            *(float4*)(a)   = *(const float4*)&As[k][rbase];
            *(float4*)(a+4) = *(const float4*)&As[k][rbase+4];
            *(float4*)(b)   = *(const float4*)&Bs[k][cbase];
            *(float4*)(b+4) = *(const float4*)&Bs[k][cbase+4];
            #pragma unroll
            for (int i = 0; i < 8; i++)
                #pragma unroll
                for (int j = 0; j < 8; j++)
                    acc[i][j] += a[i]*b[j];
        }
        __syncthreads();
    }

    const int row0 = by*GT + rbase;
    const int col0 = bx*GT + cbase;
    #pragma unroll
    for (int i = 0; i < 8; i++) {
        float4* p = (float4*)(C + (size_t)(row0+i)*N + col0);
        p[0] = make_float4(acc[i][0], acc[i][1], acc[i][2], acc[i][3]);
        p[1] = make_float4(acc[i][4], acc[i][5], acc[i][6], acc[i][7]);
    }
}

// ==================== fused per-head RMSNorm + RoPE ========================
// grid: (T, Hn+HKVn), block: 128 threads (one per dim)
__global__ __launch_bounds__(128) void rmsrope(float* __restrict__ q,
                                               float* __restrict__ k,
                                               const float* __restrict__ cosT,
                                               const float* __restrict__ sinT,
                                               const float* __restrict__ qw,
                                               const float* __restrict__ kw)
{
    const int t = blockIdx.x;          // token
    const int h = blockIdx.y;          // 0..15 q heads, 16..19 k heads
    const int d = threadIdx.x;         // 0..127
    const bool isq = (h < Hn);
    float* base = isq ? (q + (size_t)t*(Hn*Dn) + h*Dn)
                      : (k + (size_t)t*(HKVn*Dn) + (h-Hn)*Dn);
    const float* w = isq ? qw : kw;

    float v = base[d];
    float ss = v*v;
    #pragma unroll
    for (int o = 16; o; o >>= 1) ss += __shfl_xor_sync(0xffffffffu, ss, o);
    __shared__ float red[4];
    if ((d & 31) == 0) red[d >> 5] = ss;
    __syncthreads();
    float tot = red[0] + red[1] + red[2] + red[3];
    float inv = rsqrtf(tot * (1.0f/128.0f) + 1e-6f);
    float nv = v * inv * w[d];

    __shared__ float sh[128];
    sh[d] = nv;
    __syncthreads();
    float rot = (d < 64) ? -sh[d+64] : sh[d-64];
    const int s = t & (Sn-1);
    base[d] = nv * cosT[(size_t)s*Dn + d] + rot * sinT[(size_t)s*Dn + d];
}

// ==================== causal flash attention (fp32) ========================
// grid: (S/64, H, B), block 256. BQ=BKV=64, D=128.
// Padded smem rows (132 floats) so the hot LDS.128 are bank-conflict-free.
#define FROW 132            // padded row length (floats)

__global__ __launch_bounds__(256) void flash_attn(const float* __restrict__ q,
                                                  const float* __restrict__ k,
                                                  const float* __restrict__ v,
                                                  float* __restrict__ o)
{
    extern __shared__ float sm[];
    float* Qs = sm;                          // 64 * 132
    float* Ks = Qs + 64*FROW;                // 64 * 132
    float* Vs = Ks + 64*FROW;                // 64 * 132
    float* Ps = Vs + 64*FROW;                // 64 * 65

    const int qt  = blockIdx.x;              // q tile 0..31
    const int h   = blockIdx.y;              // q head
    const int b   = blockIdx.z;
    const int kvh = h >> 2;                  // GQA group-of-4
    const int tid = threadIdx.x;
    const int r   = tid >> 2;                // row within q tile (0..63)
    const int ql  = tid & 3;                 // quad lane
    const float scale = 0.08838834764831845f;   // D^-0.5

    // load Q tile [64][128]
    #pragma unroll
    for (int i = 0; i < 8; i++) {
        int id = i*256 + tid;
        int row = id >> 5, c4 = id & 31;
        *(float4*)(Qs + row*FROW + c4*4) =
            *(const float4*)(q + ((size_t)(b*Sn + qt*64 + row))*(Hn*Dn) + h*Dn + c4*4);
    }

    float m = -1e30f, l = 0.f;
    float acc[8][4];
    #pragma unroll
    for (int i = 0; i < 8; i++)
        #pragma unroll
        for (int j = 0; j < 4; j++) acc[i][j] = 0.f;

    for (int kt = 0; kt <= qt; kt++) {
        __syncthreads();   // previous tile fully consumed
        #pragma unroll
        for (int i = 0; i < 8; i++) {
            int id = i*256 + tid;
            int row = id >> 5, c4 = id & 31;
            size_t g = ((size_t)(b*Sn + kt*64 + row))*(HKVn*Dn) + kvh*Dn + c4*4;
            *(float4*)(Ks + row*FROW + c4*4) = *(const float4*)(k + g);
            *(float4*)(Vs + row*FROW + c4*4) = *(const float4*)(v + g);
        }
        __syncthreads();

        // scores: thread handles j = jj*4 + ql, jj=0..15, for its row r
        float s[16];
        #pragma unroll
        for (int jj = 0; jj < 16; jj++) s[jj] = 0.f;
        const float4* Q4 = (const float4*)(Qs + r*FROW);
        #pragma unroll 8
        for (int k4 = 0; k4 < 32; k4++) {
            float4 qv = Q4[k4];
            #pragma unroll
            for (int jj = 0; jj < 16; jj++) {
                const float4 kv = *(const float4*)(Ks + (jj*4+ql)*FROW + k4*4);
                s[jj] += qv.x*kv.x + qv.y*kv.y + qv.z*kv.z + qv.w*kv.w;
            }
        }

        const bool diag = (kt == qt);
        float mloc = -1e30f;
        #pragma unroll
        for (int jj = 0; jj < 16; jj++) {
            int j = jj*4 + ql;
            float sv = s[jj]*scale;
            if (diag && j > r) sv = -1e30f;
            s[jj] = sv;
            mloc = fmaxf(mloc, sv);
        }
        mloc = fmaxf(mloc, __shfl_xor_sync(0xffffffffu, mloc, 1));
        mloc = fmaxf(mloc, __shfl_xor_sync(0xffffffffu, mloc, 2));
        const float mnew = fmaxf(m, mloc);
        const float corr = __expf(m - mnew);

        float psum = 0.f;
        #pragma unroll
        for (int jj = 0; jj < 16; jj++) {
            float p = __expf(s[jj] - mnew);
            Ps[r*65 + jj*4 + ql] = p;
            psum += p;
        }
        psum += __shfl_xor_sync(0xffffffffu, psum, 1);
        psum += __shfl_xor_sync(0xffffffffu, psum, 2);
        l = l*corr + psum;
        m = mnew;
        #pragma unroll
        for (int c4 = 0; c4 < 8; c4++) {
            acc[c4][0] *= corr; acc[c4][1] *= corr;
            acc[c4][2] *= corr; acc[c4][3] *= corr;
        }
        __syncwarp();   // Ps written by quad lanes, read cross-lane below

        // PV: thread accumulates cols {c4*16 + ql*4 .. +3}, c4=0..7
        #pragma unroll 4
        for (int j = 0; j < 64; j++) {
            float p = Ps[r*65 + j];
            #pragma unroll
            for (int c4 = 0; c4 < 8; c4++) {
                const float4 vv = *(const float4*)(Vs + j*FROW + c4*16 + ql*4);
                acc[c4][0] += p*vv.x; acc[c4][1] += p*vv.y;
                acc[c4][2] += p*vv.z; acc[c4][3] += p*vv.w;
            }
        }
        __syncwarp();
    }

    const float invl = 1.f / l;
    float* ob = o + ((size_t)(b*Sn + qt*64 + r))*(Hn*Dn) + h*Dn;
    #pragma unroll
    for (int c4 = 0; c4 < 8; c4++) {
        *(float4*)(ob + c4*16 + ql*4) =
            make_float4(acc[c4][0]*invl, acc[c4][1]*invl,
                        acc[c4][2]*invl, acc[c4][3]*invl);
    }
}

// ==================== launch =============================================
extern "C" void kernel_launch(void* const* d_in, const int* in_sizes, int n_in,
                              void* d_out, int out_size)
{
    const float* x    = (const float*)d_in[0];   // [B,S,HS]
    const float* cosT = (const float*)d_in[1];   // [S,D]
    const float* sinT = (const float*)d_in[2];   // [S,D]
    // d_in[3] = mask (exact causal -1e9 triu) -> implemented analytically
    const float* wq   = (const float*)d_in[4];   // [H*D, HS]
    const float* wk   = (const float*)d_in[5];   // [HKV*D, HS]
    const float* wv   = (const float*)d_in[6];   // [HKV*D, HS]
    const float* wo   = (const float*)d_in[7];   // [HS, H*D]
    const float* qw   = (const float*)d_in[8];   // [D]
    const float* kw   = (const float*)d_in[9];   // [D]
    float* out = (float*)d_out;                  // [B,S,HS]

    float *q, *k, *v, *ao;
    cudaGetSymbolAddress((void**)&q,  g_q);
    cudaGetSymbolAddress((void**)&k,  g_k);
    cudaGetSymbolAddress((void**)&v,  g_v);
    cudaGetSymbolAddress((void**)&ao, g_ao);

    // QKV projections: C = X * W^T
    gemm_nt<<<dim3((Hn*Dn)/GT,   Tn/GT), 256>>>(x, wq, q, Tn, Hn*Dn,   HSn);
    gemm_nt<<<dim3((HKVn*Dn)/GT, Tn/GT), 256>>>(x, wk, k, Tn, HKVn*Dn, HSn);
    gemm_nt<<<dim3((HKVn*Dn)/GT, Tn/GT), 256>>>(x, wv, v, Tn, HKVn*Dn, HSn);

    // RMS QK-norm + RoPE (in place on q,k)
    rmsrope<<<dim3(Tn, Hn+HKVn), 128>>>(q, k, cosT, sinT, qw, kw);

    // causal flash attention
    const int smem = (3*64*FROW + 64*65) * (int)sizeof(float);   // 118016 B
    cudaFuncSetAttribute(flash_attn, cudaFuncAttributeMaxDynamicSharedMemorySize, smem);
    flash_attn<<<dim3(Sn/64, Hn, Bn), 256, smem>>>(q, k, v, ao);

    // output projection: out = AO * WO^T
    gemm_nt<<<dim3(HSn/GT, Tn/GT), 256>>>(ao, wo, out, Tn, HSn, Hn*Dn);
}

// round 5
// speedup vs baseline: 1.4169x; 1.4169x over previous
#include <cuda_runtime.h>
#include <cuda_bf16.h>
#include <math.h>
#include <stdint.h>

// Problem constants
#define Bn   2
#define Sn   2048
#define HSn  2048
#define Hn   16
#define HKVn 4
#define Dn   128
#define Tn   (Bn*Sn)          // 4096 tokens

// -------------------- scratch (device globals; allocation-free) -----------
__device__ float g_q[(size_t)Tn * (Hn*Dn)];
__device__ float g_k[(size_t)Tn * (HKVn*Dn)];
__device__ float g_v[(size_t)Tn * (HKVn*Dn)];
__device__ float g_ao[(size_t)Tn * (Hn*Dn)];

// bf16 hi/lo copies of GEMM operands
__device__ __nv_bfloat16 g_xh[(size_t)Tn*HSn],        g_xl[(size_t)Tn*HSn];
__device__ __nv_bfloat16 g_wqh[(size_t)Hn*Dn*HSn],    g_wql[(size_t)Hn*Dn*HSn];
__device__ __nv_bfloat16 g_wkh[(size_t)HKVn*Dn*HSn],  g_wkl[(size_t)HKVn*Dn*HSn];
__device__ __nv_bfloat16 g_wvh[(size_t)HKVn*Dn*HSn],  g_wvl[(size_t)HKVn*Dn*HSn];
__device__ __nv_bfloat16 g_woh[(size_t)HSn*Hn*Dn],    g_wol[(size_t)HSn*Hn*Dn];
__device__ __nv_bfloat16 g_aoh[(size_t)Tn*Hn*Dn],     g_aol[(size_t)Tn*Hn*Dn];

// ======================= helpers ==========================================
__device__ __forceinline__ uint32_t smem_u32(const void* p) {
    uint32_t a;
    asm("{ .reg .u64 t; cvta.to.shared.u64 t, %1; cvt.u32.u64 %0, t; }"
        : "=r"(a) : "l"(p));
    return a;
}
__device__ __forceinline__ void cpasync16(uint32_t dst, const void* src) {
    asm volatile("cp.async.cg.shared.global [%0], [%1], 16;" :: "r"(dst), "l"(src));
}
__device__ __forceinline__ void ldsm4(uint32_t* r, uint32_t addr) {
    asm volatile("ldmatrix.sync.aligned.m8n8.x4.shared.b16 {%0,%1,%2,%3}, [%4];"
        : "=r"(r[0]), "=r"(r[1]), "=r"(r[2]), "=r"(r[3]) : "r"(addr));
}
__device__ __forceinline__ void ldsm2(uint32_t* r, uint32_t addr) {
    asm volatile("ldmatrix.sync.aligned.m8n8.x2.shared.b16 {%0,%1}, [%2];"
        : "=r"(r[0]), "=r"(r[1]) : "r"(addr));
}
__device__ __forceinline__ void mma_bf16(float* d, const uint32_t* a, const uint32_t* b) {
    asm volatile("mma.sync.aligned.m16n8k16.row.col.f32.bf16.bf16.f32 "
                 "{%0,%1,%2,%3}, {%4,%5,%6,%7}, {%8,%9}, {%0,%1,%2,%3};"
                 : "+f"(d[0]), "+f"(d[1]), "+f"(d[2]), "+f"(d[3])
                 : "r"(a[0]), "r"(a[1]), "r"(a[2]), "r"(a[3]),
                   "r"(b[0]), "r"(b[1]));
}

// ==================== fp32 -> bf16 hi/lo conversion =======================
__global__ __launch_bounds__(256) void cvt_hilo(const float* __restrict__ x,
                                                __nv_bfloat16* __restrict__ h,
                                                __nv_bfloat16* __restrict__ l,
                                                int n4)
{
    int i = blockIdx.x*256 + threadIdx.x;
    if (i >= n4) return;
    float4 v = ((const float4*)x)[i];
    __nv_bfloat16 h0 = __float2bfloat16_rn(v.x);
    __nv_bfloat16 h1 = __float2bfloat16_rn(v.y);
    __nv_bfloat16 h2 = __float2bfloat16_rn(v.z);
    __nv_bfloat16 h3 = __float2bfloat16_rn(v.w);
    __nv_bfloat16 l0 = __float2bfloat16_rn(v.x - __bfloat162float(h0));
    __nv_bfloat16 l1 = __float2bfloat16_rn(v.y - __bfloat162float(h1));
    __nv_bfloat16 l2 = __float2bfloat16_rn(v.z - __bfloat162float(h2));
    __nv_bfloat16 l3 = __float2bfloat16_rn(v.w - __bfloat162float(h3));
    ushort4 hv = make_ushort4(__bfloat16_as_ushort(h0), __bfloat16_as_ushort(h1),
                              __bfloat16_as_ushort(h2), __bfloat16_as_ushort(h3));
    ushort4 lv = make_ushort4(__bfloat16_as_ushort(l0), __bfloat16_as_ushort(l1),
                              __bfloat16_as_ushort(l2), __bfloat16_as_ushort(l3));
    ((ushort4*)h)[i] = hv;
    ((ushort4*)l)[i] = lv;
}

// ============ HMMA GEMM: C[M,N] = A[M,K] * B[N,K]^T (split bf16) ==========
// 128x128 tile, BK=32 bf16, 256 threads (8 warps 2x4), double-buffered smem.
#define HROW 40                      // bf16 per smem row (80B stride)
#define HARR 5120                    // bf16 per array (128 rows * 40)
#define HBUF (4*HARR)                // Ah,Al,Bh,Bl  (bf16 units)
#define HSMEM (2*HBUF*2)             // bytes (two buffers)

__global__ __launch_bounds__(256, 1)
void gemm_hmma(const __nv_bfloat16* __restrict__ Ah, const __nv_bfloat16* __restrict__ Al,
               const __nv_bfloat16* __restrict__ Bh, const __nv_bfloat16* __restrict__ Bl,
               float* __restrict__ C, int M, int N, int K)
{
    extern __shared__ __nv_bfloat16 smb[];
    const uint32_t sbase = smem_u32(smb);

    const int tid  = threadIdx.x;
    const int lane = tid & 31;
    const int wid  = tid >> 5;
    const int m0w  = (wid >> 2) * 64;
    const int n0w  = (wid & 3) * 32;
    const int mrow0 = blockIdx.y * 128;
    const int ncol0 = blockIdx.x * 128;
    const int NC = K / 32;

    float acc[4][4][4];
    #pragma unroll
    for (int mt = 0; mt < 4; mt++)
        #pragma unroll
        for (int nt = 0; nt < 4; nt++)
            #pragma unroll
            for (int i = 0; i < 4; i++) acc[mt][nt][i] = 0.f;

    // chunk loader: 512 16B-chunks per array, 2 per thread per array
    auto load_chunk = [&](int c, int buf) {
        const int k0 = c * 32;
        const uint32_t b0 = sbase + (uint32_t)buf * (HBUF*2);
        #pragma unroll
        for (int i = 0; i < 2; i++) {
            int id  = i*256 + tid;          // 0..511
            int row = id >> 2;
            int cc  = id & 3;
            uint32_t d  = (uint32_t)(row*80 + cc*16);
            size_t   ga = (size_t)(mrow0 + row)*K + k0 + cc*8;
            size_t   gb = (size_t)(ncol0 + row)*K + k0 + cc*8;
            cpasync16(b0 + 0*HARR*2 + d, Ah + ga);
            cpasync16(b0 + 1*HARR*2 + d, Al + ga);
            cpasync16(b0 + 2*HARR*2 + d, Bh + gb);
            cpasync16(b0 + 3*HARR*2 + d, Bl + gb);
        }
        asm volatile("cp.async.commit_group;" ::: "memory");
    };

    load_chunk(0, 0);

    for (int c = 0; c < NC; c++) {
        const int buf = c & 1;
        if (c + 1 < NC) {
            load_chunk(c + 1, buf ^ 1);
            asm volatile("cp.async.wait_group 1;" ::: "memory");
        } else {
            asm volatile("cp.async.wait_group 0;" ::: "memory");
        }
        __syncthreads();

        const uint32_t b0  = sbase + (uint32_t)buf * (HBUF*2);
        const uint32_t aHi = b0 + 0*HARR*2;
        const uint32_t aLo = b0 + 1*HARR*2;
        const uint32_t bHi = b0 + 2*HARR*2;
        const uint32_t bLo = b0 + 3*HARR*2;

        #pragma unroll
        for (int ks = 0; ks < 2; ks++) {
            uint32_t ah[4][4], al[4][4], bh[4][2], bl[4][2];
            const uint32_t aoff = (uint32_t)(ks*32 + (lane >> 4)*16);
            const uint32_t boff = (uint32_t)(ks*32 + ((lane >> 3) & 1)*16);
            #pragma unroll
            for (int mt = 0; mt < 4; mt++) {
                uint32_t r = (uint32_t)((m0w + mt*16 + (lane & 15)) * 80) + aoff;
                ldsm4(ah[mt], aHi + r);
                ldsm4(al[mt], aLo + r);
            }
            #pragma unroll
            for (int nt = 0; nt < 4; nt++) {
                uint32_t r = (uint32_t)((n0w + nt*8 + (lane & 7)) * 80) + boff;
                ldsm2(bh[nt], bHi + r);
                ldsm2(bl[nt], bLo + r);
            }
            #pragma unroll
            for (int mt = 0; mt < 4; mt++)
                #pragma unroll
                for (int nt = 0; nt < 4; nt++) {
                    mma_bf16(acc[mt][nt], ah[mt], bh[nt]);
                    mma_bf16(acc[mt][nt], ah[mt], bl[nt]);
                    mma_bf16(acc[mt][nt], al[mt], bh[nt]);
                }
        }
        __syncthreads();
    }

    // epilogue
    #pragma unroll
    for (int mt = 0; mt < 4; mt++)
        #pragma unroll
        for (int nt = 0; nt < 4; nt++) {
            const float* d = acc[mt][nt];
            int row = mrow0 + m0w + mt*16 + (lane >> 2);
            int col = ncol0 + n0w + nt*8 + (lane & 3)*2;
            *(float2*)(C + (size_t)row*N + col)     = make_float2(d[0], d[1]);
            *(float2*)(C + (size_t)(row+8)*N + col) = make_float2(d[2], d[3]);
        }
}

// ==================== fused per-head RMSNorm + RoPE ========================
__global__ __launch_bounds__(128) void rmsrope(float* __restrict__ q,
                                               float* __restrict__ k,
                                               const float* __restrict__ cosT,
                                               const float* __restrict__ sinT,
                                               const float* __restrict__ qw,
                                               const float* __restrict__ kw)
{
    const int t = blockIdx.x;
    const int h = blockIdx.y;
    const int d = threadIdx.x;
    const bool isq = (h < Hn);
    float* base = isq ? (q + (size_t)t*(Hn*Dn) + h*Dn)
                      : (k + (size_t)t*(HKVn*Dn) + (h-Hn)*Dn);
    const float* w = isq ? qw : kw;

    float v = base[d];
    float ss = v*v;
    #pragma unroll
    for (int o = 16; o; o >>= 1) ss += __shfl_xor_sync(0xffffffffu, ss, o);
    __shared__ float red[4];
    if ((d & 31) == 0) red[d >> 5] = ss;
    __syncthreads();
    float tot = red[0] + red[1] + red[2] + red[3];
    float inv = rsqrtf(tot * (1.0f/128.0f) + 1e-6f);
    float nv = v * inv * w[d];

    __shared__ float sh[128];
    sh[d] = nv;
    __syncthreads();
    float rot = (d < 64) ? -sh[d+64] : sh[d-64];
    const int s = t & (Sn-1);
    base[d] = nv * cosT[(size_t)s*Dn + d] + rot * sinT[(size_t)s*Dn + d];
}

// ==================== causal flash attention (fp32) ========================
#define FROW 132

__global__ __launch_bounds__(256) void flash_attn(const float* __restrict__ q,
                                                  const float* __restrict__ k,
                                                  const float* __restrict__ v,
                                                  float* __restrict__ o)
{
    extern __shared__ float smf[];
    float* Qs = smf;
    float* Ks = Qs + 64*FROW;
    float* Vs = Ks + 64*FROW;
    float* Ps = Vs + 64*FROW;

    const int qt  = blockIdx.x;
    const int h   = blockIdx.y;
    const int b   = blockIdx.z;
    const int kvh = h >> 2;
    const int tid = threadIdx.x;
    const int r   = tid >> 2;
    const int ql  = tid & 3;
    const float scale = 0.08838834764831845f;

    #pragma unroll
    for (int i = 0; i < 8; i++) {
        int id = i*256 + tid;
        int row = id >> 5, c4 = id & 31;
        *(float4*)(Qs + row*FROW + c4*4) =
            *(const float4*)(q + ((size_t)(b*Sn + qt*64 + row))*(Hn*Dn) + h*Dn + c4*4);
    }

    float m = -1e30f, l = 0.f;
    float acc[8][4];
    #pragma unroll
    for (int i = 0; i < 8; i++)
        #pragma unroll
        for (int j = 0; j < 4; j++) acc[i][j] = 0.f;

    for (int kt = 0; kt <= qt; kt++) {
        __syncthreads();
        #pragma unroll
        for (int i = 0; i < 8; i++) {
            int id = i*256 + tid;
            int row = id >> 5, c4 = id & 31;
            size_t g = ((size_t)(b*Sn + kt*64 + row))*(HKVn*Dn) + kvh*Dn + c4*4;
            *(float4*)(Ks + row*FROW + c4*4) = *(const float4*)(k + g);
            *(float4*)(Vs + row*FROW + c4*4) = *(const float4*)(v + g);
        }
        __syncthreads();

        float s[16];
        #pragma unroll
        for (int jj = 0; jj < 16; jj++) s[jj] = 0.f;
        const float4* Q4 = (const float4*)(Qs + r*FROW);
        #pragma unroll 8
        for (int k4 = 0; k4 < 32; k4++) {
            float4 qv = Q4[k4];
            #pragma unroll
            for (int jj = 0; jj < 16; jj++) {
                const float4 kv = *(const float4*)(Ks + (jj*4+ql)*FROW + k4*4);
                s[jj] += qv.x*kv.x + qv.y*kv.y + qv.z*kv.z + qv.w*kv.w;
            }
        }

        const bool diag = (kt == qt);
        float mloc = -1e30f;
        #pragma unroll
        for (int jj = 0; jj < 16; jj++) {
            int j = jj*4 + ql;
            float sv = s[jj]*scale;
            if (diag && j > r) sv = -1e30f;
            s[jj] = sv;
            mloc = fmaxf(mloc, sv);
        }
        mloc = fmaxf(mloc, __shfl_xor_sync(0xffffffffu, mloc, 1));
        mloc = fmaxf(mloc, __shfl_xor_sync(0xffffffffu, mloc, 2));
        const float mnew = fmaxf(m, mloc);
        const float corr = __expf(m - mnew);

        float psum = 0.f;
        #pragma unroll
        for (int jj = 0; jj < 16; jj++) {
            float p = __expf(s[jj] - mnew);
            Ps[r*65 + jj*4 + ql] = p;
            psum += p;
        }
        psum += __shfl_xor_sync(0xffffffffu, psum, 1);
        psum += __shfl_xor_sync(0xffffffffu, psum, 2);
        l = l*corr + psum;
        m = mnew;
        #pragma unroll
        for (int c4 = 0; c4 < 8; c4++) {
            acc[c4][0] *= corr; acc[c4][1] *= corr;
            acc[c4][2] *= corr; acc[c4][3] *= corr;
        }
        __syncwarp();

        #pragma unroll 4
        for (int j = 0; j < 64; j++) {
            float p = Ps[r*65 + j];
            #pragma unroll
            for (int c4 = 0; c4 < 8; c4++) {
                const float4 vv = *(const float4*)(Vs + j*FROW + c4*16 + ql*4);
                acc[c4][0] += p*vv.x; acc[c4][1] += p*vv.y;
                acc[c4][2] += p*vv.z; acc[c4][3] += p*vv.w;
            }
        }
        __syncwarp();
    }

    const float invl = 1.f / l;
    float* ob = o + ((size_t)(b*Sn + qt*64 + r))*(Hn*Dn) + h*Dn;
    #pragma unroll
    for (int c4 = 0; c4 < 8; c4++) {
        *(float4*)(ob + c4*16 + ql*4) =
            make_float4(acc[c4][0]*invl, acc[c4][1]*invl,
                        acc[c4][2]*invl, acc[c4][3]*invl);
    }
}

// ==================== launch =============================================
static inline void cvt(const float* src, __nv_bfloat16* h, __nv_bfloat16* l, size_t n) {
    int n4 = (int)(n / 4);
    cvt_hilo<<<(n4 + 255)/256, 256>>>(src, h, l, n4);
}

extern "C" void kernel_launch(void* const* d_in, const int* in_sizes, int n_in,
                              void* d_out, int out_size)
{
    const float* x    = (const float*)d_in[0];
    const float* cosT = (const float*)d_in[1];
    const float* sinT = (const float*)d_in[2];
    // d_in[3] = mask (exact causal -1e9 triu) -> applied analytically
    const float* wq   = (const float*)d_in[4];
    const float* wk   = (const float*)d_in[5];
    const float* wv   = (const float*)d_in[6];
    const float* wo   = (const float*)d_in[7];
    const float* qw   = (const float*)d_in[8];
    const float* kw   = (const float*)d_in[9];
    float* out = (float*)d_out;

    float *q, *k, *v, *ao;
    cudaGetSymbolAddress((void**)&q,  g_q);
    cudaGetSymbolAddress((void**)&k,  g_k);
    cudaGetSymbolAddress((void**)&v,  g_v);
    cudaGetSymbolAddress((void**)&ao, g_ao);

    __nv_bfloat16 *xh, *xl, *wqh, *wql, *wkh, *wkl, *wvh, *wvl, *woh, *wol, *aoh, *aol;
    cudaGetSymbolAddress((void**)&xh,  g_xh);  cudaGetSymbolAddress((void**)&xl,  g_xl);
    cudaGetSymbolAddress((void**)&wqh, g_wqh); cudaGetSymbolAddress((void**)&wql, g_wql);
    cudaGetSymbolAddress((void**)&wkh, g_wkh); cudaGetSymbolAddress((void**)&wkl, g_wkl);
    cudaGetSymbolAddress((void**)&wvh, g_wvh); cudaGetSymbolAddress((void**)&wvl, g_wvl);
    cudaGetSymbolAddress((void**)&woh, g_woh); cudaGetSymbolAddress((void**)&wol, g_wol);
    cudaGetSymbolAddress((void**)&aoh, g_aoh); cudaGetSymbolAddress((void**)&aol, g_aol);

    // hi/lo conversions for GEMM operands
    cvt(x,  xh,  xl,  (size_t)Tn*HSn);
    cvt(wq, wqh, wql, (size_t)Hn*Dn*HSn);
    cvt(wk, wkh, wkl, (size_t)HKVn*Dn*HSn);
    cvt(wv, wvh, wvl, (size_t)HKVn*Dn*HSn);
    cvt(wo, woh, wol, (size_t)HSn*Hn*Dn);

    cudaFuncSetAttribute(gemm_hmma, cudaFuncAttributeMaxDynamicSharedMemorySize, HSMEM);

    // QKV projections (HMMA split-bf16)
    gemm_hmma<<<dim3((Hn*Dn)/128,   Tn/128), 256, HSMEM>>>(xh, xl, wqh, wql, q, Tn, Hn*Dn,   HSn);
    gemm_hmma<<<dim3((HKVn*Dn)/128, Tn/128), 256, HSMEM>>>(xh, xl, wkh, wkl, k, Tn, HKVn*Dn, HSn);
    gemm_hmma<<<dim3((HKVn*Dn)/128, Tn/128), 256, HSMEM>>>(xh, xl, wvh, wvl, v, Tn, HKVn*Dn, HSn);

    // RMS QK-norm + RoPE (in place on q,k)
    rmsrope<<<dim3(Tn, Hn+HKVn), 128>>>(q, k, cosT, sinT, qw, kw);

    // causal flash attention (fp32)
    const int fsmem = (3*64*FROW + 64*65) * (int)sizeof(float);
    cudaFuncSetAttribute(flash_attn, cudaFuncAttributeMaxDynamicSharedMemorySize, fsmem);
    flash_attn<<<dim3(Sn/64, Hn, Bn), 256, fsmem>>>(q, k, v, ao);

    // output projection
    cvt(ao, aoh, aol, (size_t)Tn*Hn*Dn);
    gemm_hmma<<<dim3(HSn/128, Tn/128), 256, HSMEM>>>(aoh, aol, woh, wol, out, Tn, HSn, Hn*Dn);
}

// round 12
// speedup vs baseline: 3.5204x; 2.4846x over previous
#include <cuda_runtime.h>
#include <cuda_bf16.h>
#include <math.h>
#include <stdint.h>

// Problem constants
#define Bn   2
#define Sn   2048
#define HSn  2048
#define Hn   16
#define HKVn 4
#define Dn   128
#define Tn   (Bn*Sn)          // 4096 tokens

// -------------------- scratch (device globals; allocation-free) -----------
__device__ float g_q[(size_t)Tn * (Hn*Dn)];
__device__ float g_k[(size_t)Tn * (HKVn*Dn)];
__device__ float g_v[(size_t)Tn * (HKVn*Dn)];

__device__ __nv_bfloat16 g_xh[(size_t)Tn*HSn],        g_xl[(size_t)Tn*HSn];
__device__ __nv_bfloat16 g_wqh[(size_t)Hn*Dn*HSn],    g_wql[(size_t)Hn*Dn*HSn];
__device__ __nv_bfloat16 g_wkh[(size_t)HKVn*Dn*HSn],  g_wkl[(size_t)HKVn*Dn*HSn];
__device__ __nv_bfloat16 g_wvh[(size_t)HKVn*Dn*HSn],  g_wvl[(size_t)HKVn*Dn*HSn];
__device__ __nv_bfloat16 g_woh[(size_t)HSn*Hn*Dn],    g_wol[(size_t)HSn*Hn*Dn];
// post-norm/rope Q,K and V in bf16 hi/lo for the flash kernel
__device__ __nv_bfloat16 g_qbh[(size_t)Tn*Hn*Dn],     g_qbl[(size_t)Tn*Hn*Dn];
__device__ __nv_bfloat16 g_kbh[(size_t)Tn*HKVn*Dn],   g_kbl[(size_t)Tn*HKVn*Dn];
__device__ __nv_bfloat16 g_vbh[(size_t)Tn*HKVn*Dn],   g_vbl[(size_t)Tn*HKVn*Dn];
// attention output hi/lo for the O-projection
__device__ __nv_bfloat16 g_aoh[(size_t)Tn*Hn*Dn],     g_aol[(size_t)Tn*Hn*Dn];

// ======================= helpers ==========================================
__device__ __forceinline__ uint32_t smem_u32(const void* p) {
    uint32_t a;
    asm("{ .reg .u64 t; cvta.to.shared.u64 t, %1; cvt.u32.u64 %0, t; }"
        : "=r"(a) : "l"(p));
    return a;
}
__device__ __forceinline__ void cpasync16(uint32_t dst, const void* src) {
    asm volatile("cp.async.cg.shared.global [%0], [%1], 16;" :: "r"(dst), "l"(src));
}
#define CP_COMMIT() asm volatile("cp.async.commit_group;" ::: "memory")
__device__ __forceinline__ void ldsm4(uint32_t* r, uint32_t addr) {
    asm volatile("ldmatrix.sync.aligned.m8n8.x4.shared.b16 {%0,%1,%2,%3}, [%4];"
        : "=r"(r[0]), "=r"(r[1]), "=r"(r[2]), "=r"(r[3]) : "r"(addr));
}
__device__ __forceinline__ void ldsm4t(uint32_t* r, uint32_t addr) {
    asm volatile("ldmatrix.sync.aligned.m8n8.x4.trans.shared.b16 {%0,%1,%2,%3}, [%4];"
        : "=r"(r[0]), "=r"(r[1]), "=r"(r[2]), "=r"(r[3]) : "r"(addr));
}
__device__ __forceinline__ void mma_bf16(float* d, const uint32_t* a, const uint32_t* b) {
    asm volatile("mma.sync.aligned.m16n8k16.row.col.f32.bf16.bf16.f32 "
                 "{%0,%1,%2,%3}, {%4,%5,%6,%7}, {%8,%9}, {%0,%1,%2,%3};"
                 : "+f"(d[0]), "+f"(d[1]), "+f"(d[2]), "+f"(d[3])
                 : "r"(a[0]), "r"(a[1]), "r"(a[2]), "r"(a[3]),
                   "r"(b[0]), "r"(b[1]));
}
__device__ __forceinline__ uint32_t packbf(__nv_bfloat16 a, __nv_bfloat16 b) {
    return (uint32_t)__bfloat16_as_ushort(a) |
           ((uint32_t)__bfloat16_as_ushort(b) << 16);
}

// ==================== fp32 -> bf16 hi/lo conversion =======================
__global__ __launch_bounds__(256) void cvt_hilo(const float* __restrict__ x,
                                                __nv_bfloat16* __restrict__ h,
                                                __nv_bfloat16* __restrict__ l,
                                                int n4)
{
    int i = blockIdx.x*256 + threadIdx.x;
    if (i >= n4) return;
    float4 v = ((const float4*)x)[i];
    __nv_bfloat16 h0 = __float2bfloat16_rn(v.x);
    __nv_bfloat16 h1 = __float2bfloat16_rn(v.y);
    __nv_bfloat16 h2 = __float2bfloat16_rn(v.z);
    __nv_bfloat16 h3 = __float2bfloat16_rn(v.w);
    __nv_bfloat16 l0 = __float2bfloat16_rn(v.x - __bfloat162float(h0));
    __nv_bfloat16 l1 = __float2bfloat16_rn(v.y - __bfloat162float(h1));
    __nv_bfloat16 l2 = __float2bfloat16_rn(v.z - __bfloat162float(h2));
    __nv_bfloat16 l3 = __float2bfloat16_rn(v.w - __bfloat162float(h3));
    ((ushort4*)h)[i] = make_ushort4(__bfloat16_as_ushort(h0), __bfloat16_as_ushort(h1),
                                    __bfloat16_as_ushort(h2), __bfloat16_as_ushort(h3));
    ((ushort4*)l)[i] = make_ushort4(__bfloat16_as_ushort(l0), __bfloat16_as_ushort(l1),
                                    __bfloat16_as_ushort(l2), __bfloat16_as_ushort(l3));
}

// ============ HMMA GEMM: C[M,N] = A[M,K] * B[N,K]^T (split bf16) ==========
// 128x128 tile, BK=32, 256 threads (8 warps 2x4), 3-stage cp.async pipeline.
#define HARR 5120                    // bf16 per array (128 rows * 40)
#define HSTG (4*HARR*2)              // bytes per stage (Ah,Al,Bh,Bl)
#define HSMEM (3*HSTG)               // 122880 B

__global__ __launch_bounds__(256, 1)
void gemm_hmma(const __nv_bfloat16* __restrict__ Ah, const __nv_bfloat16* __restrict__ Al,
               const __nv_bfloat16* __restrict__ Bh, const __nv_bfloat16* __restrict__ Bl,
               float* __restrict__ C, int M, int N, int K,
               const __nv_bfloat16* Bh2, const __nv_bfloat16* Bl2,
               float* C2, int nx1)
{
    extern __shared__ __nv_bfloat16 smb[];
    const uint32_t sbase = smem_u32(smb);

    int bx = blockIdx.x;
    const __nv_bfloat16 *pBh = Bh, *pBl = Bl;
    float* pC = C;
    if (bx >= nx1) { bx -= nx1; pBh = Bh2; pBl = Bl2; pC = C2; }

    const int tid  = threadIdx.x;
    const int lane = tid & 31;
    const int wid  = tid >> 5;
    const int m0w  = (wid >> 2) * 64;
    const int n0w  = (wid & 3) * 32;
    const int mrow0 = blockIdx.y * 128;
    const int ncol0 = bx * 128;
    const int NC = K / 32;

    float acc[4][4][4];
    #pragma unroll
    for (int mt = 0; mt < 4; mt++)
        #pragma unroll
        for (int nt = 0; nt < 4; nt++)
            #pragma unroll
            for (int i = 0; i < 4; i++) acc[mt][nt][i] = 0.f;

    auto load_chunk = [&](int c, int st) {
        const int k0 = c * 32;
        const uint32_t b0 = sbase + (uint32_t)st * HSTG;
        #pragma unroll
        for (int i = 0; i < 2; i++) {
            int id  = i*256 + tid;
            int row = id >> 2;
            int cc  = id & 3;
            uint32_t d  = (uint32_t)(row*80 + cc*16);
            size_t   ga = (size_t)(mrow0 + row)*K + k0 + cc*8;
            size_t   gb = (size_t)(ncol0 + row)*K + k0 + cc*8;
            cpasync16(b0 + 0*HARR*2 + d, Ah  + ga);
            cpasync16(b0 + 1*HARR*2 + d, Al  + ga);
            cpasync16(b0 + 2*HARR*2 + d, pBh + gb);
            cpasync16(b0 + 3*HARR*2 + d, pBl + gb);
        }
        CP_COMMIT();
    };

    load_chunk(0, 0);
    load_chunk(1, 1);

    for (int c = 0; c < NC; c++) {
        if (c + 1 < NC) asm volatile("cp.async.wait_group 1;" ::: "memory");
        else            asm volatile("cp.async.wait_group 0;" ::: "memory");
        __syncthreads();
        if (c + 2 < NC) load_chunk(c + 2, (c + 2) % 3);

        const uint32_t b0  = sbase + (uint32_t)(c % 3) * HSTG;
        const uint32_t aHi = b0 + 0*HARR*2;
        const uint32_t aLo = b0 + 1*HARR*2;
        const uint32_t bHi = b0 + 2*HARR*2;
        const uint32_t bLo = b0 + 3*HARR*2;

        #pragma unroll
        for (int ks = 0; ks < 2; ks++) {
            uint32_t ah[4][4], al[4][4], bh[2][4], bl[2][4];
            const uint32_t aoff = (uint32_t)(ks*32 + (lane >> 4)*16);
            const uint32_t boff = (uint32_t)(ks*32 + ((lane >> 3) & 1)*16);
            #pragma unroll
            for (int mt = 0; mt < 4; mt++) {
                uint32_t r = (uint32_t)((m0w + mt*16 + (lane & 15)) * 80) + aoff;
                ldsm4(ah[mt], aHi + r);
                ldsm4(al[mt], aLo + r);
            }
            #pragma unroll
            for (int n2 = 0; n2 < 2; n2++) {
                uint32_t r = (uint32_t)((n0w + n2*16 + ((lane>>4)<<3) + (lane & 7)) * 80) + boff;
                ldsm4(bh[n2], bHi + r);
                ldsm4(bl[n2], bLo + r);
            }
            // term-major MMA ordering (RAW distance 16)
            #pragma unroll
            for (int mt = 0; mt < 4; mt++)
                #pragma unroll
                for (int nt = 0; nt < 4; nt++)
                    mma_bf16(acc[mt][nt], ah[mt], &bh[nt>>1][(nt&1)*2]);
            #pragma unroll
            for (int mt = 0; mt < 4; mt++)
                #pragma unroll
                for (int nt = 0; nt < 4; nt++)
                    mma_bf16(acc[mt][nt], ah[mt], &bl[nt>>1][(nt&1)*2]);
            #pragma unroll
            for (int mt = 0; mt < 4; mt++)
                #pragma unroll
                for (int nt = 0; nt < 4; nt++)
                    mma_bf16(acc[mt][nt], al[mt], &bh[nt>>1][(nt&1)*2]);
        }
        __syncthreads();
    }

    #pragma unroll
    for (int mt = 0; mt < 4; mt++)
        #pragma unroll
        for (int nt = 0; nt < 4; nt++) {
            const float* d = acc[mt][nt];
            int row = mrow0 + m0w + mt*16 + (lane >> 2);
            int col = ncol0 + n0w + nt*8 + (lane & 3)*2;
            *(float2*)(pC + (size_t)row*N + col)     = make_float2(d[0], d[1]);
            *(float2*)(pC + (size_t)(row+8)*N + col) = make_float2(d[2], d[3]);
        }
}

// ===== fused per-head RMSNorm + RoPE -> bf16 hi/lo outputs ================
__global__ __launch_bounds__(128) void rmsrope(const float* __restrict__ q,
                                               const float* __restrict__ k,
                                               const float* __restrict__ cosT,
                                               const float* __restrict__ sinT,
                                               const float* __restrict__ qw,
                                               const float* __restrict__ kw,
                                               __nv_bfloat16* __restrict__ qh,
                                               __nv_bfloat16* __restrict__ ql,
                                               __nv_bfloat16* __restrict__ kh,
                                               __nv_bfloat16* __restrict__ kl)
{
    const int t = blockIdx.x;
    const int h = blockIdx.y;
    const int d = threadIdx.x;
    const bool isq = (h < Hn);
    const float* base = isq ? (q + (size_t)t*(Hn*Dn) + h*Dn)
                            : (k + (size_t)t*(HKVn*Dn) + (h-Hn)*Dn);
    const float* w = isq ? qw : kw;

    float v = base[d];
    float ss = v*v;
    #pragma unroll
    for (int o = 16; o; o >>= 1) ss += __shfl_xor_sync(0xffffffffu, ss, o);
    __shared__ float red[4];
    if ((d & 31) == 0) red[d >> 5] = ss;
    __syncthreads();
    float tot = red[0] + red[1] + red[2] + red[3];
    float inv = rsqrtf(tot * (1.0f/128.0f) + 1e-6f);
    float nv = v * inv * w[d];

    __shared__ float sh[128];
    sh[d] = nv;
    __syncthreads();
    float rot = (d < 64) ? -sh[d+64] : sh[d-64];
    const int s = t & (Sn-1);
    float r = nv * cosT[(size_t)s*Dn + d] + rot * sinT[(size_t)s*Dn + d];

    __nv_bfloat16 hi = __float2bfloat16_rn(r);
    __nv_bfloat16 lo = __float2bfloat16_rn(r - __bfloat162float(hi));
    if (isq) {
        size_t o1 = ((size_t)t*Hn + h)*Dn + d;
        qh[o1] = hi; ql[o1] = lo;
    } else {
        size_t o1 = ((size_t)t*HKVn + (h-Hn))*Dn + d;
        kh[o1] = hi; kl[o1] = lo;
    }
}

// ============== causal flash attention (HMMA split-bf16) ==================
// grid (16 qtiles, 16 heads, 2 batch), 256 threads, BQ=128, BKV=64, D=128.
#define FSTR 272                 // bytes per smem row (128 bf16 + 8 pad)
#define FQ_BYTES (128*FSTR)      // 34816
#define FKV_BYTES (64*FSTR)      // 17408
#define FSTAGE (4*FKV_BYTES)     // Kh,Kl,Vh,Vl = 69632
#define FSMEM (2*FQ_BYTES + 2*FSTAGE)  // 208896

__global__ __launch_bounds__(256, 1)
void flash_hmma(const __nv_bfloat16* __restrict__ qh, const __nv_bfloat16* __restrict__ qlp,
                const __nv_bfloat16* __restrict__ kh, const __nv_bfloat16* __restrict__ klp,
                const __nv_bfloat16* __restrict__ vh, const __nv_bfloat16* __restrict__ vlp,
                __nv_bfloat16* __restrict__ oh, __nv_bfloat16* __restrict__ olp)
{
    extern __shared__ char smc[];
    const uint32_t sb = smem_u32(smc);
    const uint32_t Qh = sb, Ql = sb + FQ_BYTES;

    const int qt = blockIdx.x, h = blockIdx.y, b = blockIdx.z;
    const int kvh = h >> 2;
    const int tid = threadIdx.x, lane = tid & 31, w = tid >> 5;
    const float scale = 0.08838834764831845f;

    // Q tile (hi+lo): 128 rows x 16 chunks, hi AND lo per id -> 8*256 = 2048 ids
    #pragma unroll
    for (int i = 0; i < 8; i++) {
        int id = i*256 + tid;
        int row = id >> 4, ch = id & 15;
        size_t g = ((size_t)(b*Sn + qt*128 + row)*Hn + h)*Dn + ch*8;
        uint32_t d = (uint32_t)(row*FSTR + ch*16);
        cpasync16(Qh + d, qh  + g);
        cpasync16(Ql + d, qlp + g);
    }
    CP_COMMIT();

    auto load_kv = [&](int kt, int st) {
        uint32_t base = sb + 2*FQ_BYTES + (uint32_t)st * FSTAGE;
        #pragma unroll
        for (int i = 0; i < 4; i++) {
            int id = i*256 + tid;
            int row = id >> 4, ch = id & 15;
            size_t g = ((size_t)(b*Sn + kt*64 + row)*HKVn + kvh)*Dn + ch*8;
            uint32_t d = (uint32_t)(row*FSTR + ch*16);
            cpasync16(base + 0*FKV_BYTES + d, kh  + g);
            cpasync16(base + 1*FKV_BYTES + d, klp + g);
            cpasync16(base + 2*FKV_BYTES + d, vh  + g);
            cpasync16(base + 3*FKV_BYTES + d, vlp + g);
        }
        CP_COMMIT();
    };

    const int nkv = 2*qt + 2;
    load_kv(0, 0);

    float oacc[16][4];
    #pragma unroll
    for (int i = 0; i < 16; i++)
        #pragma unroll
        for (int j = 0; j < 4; j++) oacc[i][j] = 0.f;
    float m0 = -1e30f, m1 = -1e30f, l0 = 0.f, l1 = 0.f;
    const int gr0 = qt*128 + w*16 + (lane >> 2);
    const int gr1 = gr0 + 8;

    for (int kt = 0; kt < nkv; kt++) {
        asm volatile("cp.async.wait_group 0;" ::: "memory");
        __syncthreads();
        if (kt + 1 < nkv) load_kv(kt + 1, (kt + 1) & 1);

        const uint32_t kb = sb + 2*FQ_BYTES + (uint32_t)(kt & 1) * FSTAGE;

        // ---- S = Q K^T (3-term split) ----
        float sacc[8][4];
        #pragma unroll
        for (int i = 0; i < 8; i++)
            #pragma unroll
            for (int j = 0; j < 4; j++) sacc[i][j] = 0.f;

        #pragma unroll
        for (int ks = 0; ks < 8; ks++) {
            uint32_t qhf[4], qlf[4], khf[4][4], klf[4][4];
            const uint32_t aoff = (uint32_t)(ks*32 + (lane >> 4)*16);
            const uint32_t arow = (uint32_t)((w*16 + (lane & 15)) * FSTR);
            ldsm4(qhf, Qh + arow + aoff);
            ldsm4(qlf, Ql + arow + aoff);
            const uint32_t boff = (uint32_t)(ks*32 + ((lane >> 3) & 1)*16);
            #pragma unroll
            for (int n2 = 0; n2 < 4; n2++) {
                uint32_t r = (uint32_t)((n2*16 + ((lane>>4)<<3) + (lane & 7)) * FSTR) + boff;
                ldsm4(khf[n2], kb + 0*FKV_BYTES + r);
                ldsm4(klf[n2], kb + 1*FKV_BYTES + r);
            }
            #pragma unroll
            for (int nt = 0; nt < 8; nt++)
                mma_bf16(sacc[nt], qhf, &khf[nt>>1][(nt&1)*2]);
            #pragma unroll
            for (int nt = 0; nt < 8; nt++)
                mma_bf16(sacc[nt], qhf, &klf[nt>>1][(nt&1)*2]);
            #pragma unroll
            for (int nt = 0; nt < 8; nt++)
                mma_bf16(sacc[nt], qlf, &khf[nt>>1][(nt&1)*2]);
        }

        // ---- softmax (online) ----
        const bool dz = (kt >= 2*qt);
        float mx0 = -1e30f, mx1 = -1e30f;
        #pragma unroll
        for (int nt = 0; nt < 8; nt++) {
            const int gc = kt*64 + nt*8 + (lane & 3)*2;
            float s0 = sacc[nt][0]*scale, s1 = sacc[nt][1]*scale;
            float s2 = sacc[nt][2]*scale, s3 = sacc[nt][3]*scale;
            if (dz) {
                if (gc     > gr0) s0 = -1e30f;
                if (gc + 1 > gr0) s1 = -1e30f;
                if (gc     > gr1) s2 = -1e30f;
                if (gc + 1 > gr1) s3 = -1e30f;
            }
            sacc[nt][0] = s0; sacc[nt][1] = s1; sacc[nt][2] = s2; sacc[nt][3] = s3;
            mx0 = fmaxf(mx0, fmaxf(s0, s1));
            mx1 = fmaxf(mx1, fmaxf(s2, s3));
        }
        mx0 = fmaxf(mx0, __shfl_xor_sync(0xffffffffu, mx0, 1));
        mx0 = fmaxf(mx0, __shfl_xor_sync(0xffffffffu, mx0, 2));
        mx1 = fmaxf(mx1, __shfl_xor_sync(0xffffffffu, mx1, 1));
        mx1 = fmaxf(mx1, __shfl_xor_sync(0xffffffffu, mx1, 2));
        const float mn0 = fmaxf(m0, mx0), mn1 = fmaxf(m1, mx1);
        const float cr0 = __expf(m0 - mn0), cr1 = __expf(m1 - mn1);
        m0 = mn0; m1 = mn1;

        uint32_t pha[8], phb[8], pla[8], plb[8];
        float sum0 = 0.f, sum1 = 0.f;
        #pragma unroll
        for (int nt = 0; nt < 8; nt++) {
            float p0 = __expf(sacc[nt][0] - mn0);
            float p1 = __expf(sacc[nt][1] - mn0);
            float p2 = __expf(sacc[nt][2] - mn1);
            float p3 = __expf(sacc[nt][3] - mn1);
            sum0 += p0 + p1; sum1 += p2 + p3;
            __nv_bfloat16 h0 = __float2bfloat16_rn(p0);
            __nv_bfloat16 h1 = __float2bfloat16_rn(p1);
            __nv_bfloat16 h2 = __float2bfloat16_rn(p2);
            __nv_bfloat16 h3 = __float2bfloat16_rn(p3);
            pha[nt] = packbf(h0, h1);
            phb[nt] = packbf(h2, h3);
            pla[nt] = packbf(__float2bfloat16_rn(p0 - __bfloat162float(h0)),
                             __float2bfloat16_rn(p1 - __bfloat162float(h1)));
            plb[nt] = packbf(__float2bfloat16_rn(p2 - __bfloat162float(h2)),
                             __float2bfloat16_rn(p3 - __bfloat162float(h3)));
        }
        sum0 += __shfl_xor_sync(0xffffffffu, sum0, 1);
        sum0 += __shfl_xor_sync(0xffffffffu, sum0, 2);
        sum1 += __shfl_xor_sync(0xffffffffu, sum1, 1);
        sum1 += __shfl_xor_sync(0xffffffffu, sum1, 2);
        l0 = l0*cr0 + sum0;
        l1 = l1*cr1 + sum1;
        #pragma unroll
        for (int nt = 0; nt < 16; nt++) {
            oacc[nt][0] *= cr0; oacc[nt][1] *= cr0;
            oacc[nt][2] *= cr1; oacc[nt][3] *= cr1;
        }

        // ---- O += P V (3-term split), V via ldmatrix.trans ----
        #pragma unroll
        for (int ks = 0; ks < 4; ks++) {
            uint32_t ah4[4] = { pha[2*ks], phb[2*ks], pha[2*ks+1], phb[2*ks+1] };
            uint32_t al4[4] = { pla[2*ks], plb[2*ks], pla[2*ks+1], plb[2*ks+1] };
            const uint32_t vrow = (uint32_t)((ks*16 + ((lane>>3)&1)*8 + (lane&7)) * FSTR);
            #pragma unroll
            for (int half = 0; half < 2; half++) {
                uint32_t vhf[4][4], vlf[4][4];
                #pragma unroll
                for (int n2 = 0; n2 < 4; n2++) {
                    uint32_t coff = (uint32_t)(((half*4 + n2)*2 + (lane>>4)) * 16);
                    ldsm4t(vhf[n2], kb + 2*FKV_BYTES + vrow + coff);
                    ldsm4t(vlf[n2], kb + 3*FKV_BYTES + vrow + coff);
                }
                #pragma unroll
                for (int nt = 0; nt < 8; nt++)
                    mma_bf16(oacc[half*8 + nt], ah4, &vhf[nt>>1][(nt&1)*2]);
                #pragma unroll
                for (int nt = 0; nt < 8; nt++)
                    mma_bf16(oacc[half*8 + nt], ah4, &vlf[nt>>1][(nt&1)*2]);
                #pragma unroll
                for (int nt = 0; nt < 8; nt++)
                    mma_bf16(oacc[half*8 + nt], al4, &vhf[nt>>1][(nt&1)*2]);
            }
        }
    }

    // epilogue: normalize and emit hi/lo bf16
    const float inv0 = 1.f / l0, inv1 = 1.f / l1;
    const size_t t0 = (size_t)(b*Sn + qt*128 + w*16 + (lane >> 2));
    const size_t r0base = (t0*Hn + h)*Dn;
    const size_t r1base = ((t0 + 8)*Hn + h)*Dn;
    #pragma unroll
    for (int nt = 0; nt < 16; nt++) {
        const int col = nt*8 + (lane & 3)*2;
        float o0 = oacc[nt][0]*inv0, o1 = oacc[nt][1]*inv0;
        float o2 = oacc[nt][2]*inv1, o3 = oacc[nt][3]*inv1;
        __nv_bfloat16 h0 = __float2bfloat16_rn(o0), h1 = __float2bfloat16_rn(o1);
        __nv_bfloat16 h2 = __float2bfloat16_rn(o2), h3 = __float2bfloat16_rn(o3);
        *(uint32_t*)(oh  + r0base + col) = packbf(h0, h1);
        *(uint32_t*)(oh  + r1base + col) = packbf(h2, h3);
        *(uint32_t*)(olp + r0base + col) =
            packbf(__float2bfloat16_rn(o0 - __bfloat162float(h0)),
                   __float2bfloat16_rn(o1 - __bfloat162float(h1)));
        *(uint32_t*)(olp + r1base + col) =
            packbf(__float2bfloat16_rn(o2 - __bfloat162float(h2)),
                   __float2bfloat16_rn(o3 - __bfloat162float(h3)));
    }
}

// ==================== launch =============================================
static inline void cvt(const float* src, __nv_bfloat16* h, __nv_bfloat16* l, size_t n) {
    int n4 = (int)(n / 4);
    cvt_hilo<<<(n4 + 255)/256, 256>>>(src, h, l, n4);
}

extern "C" void kernel_launch(void* const* d_in, const int* in_sizes, int n_in,
                              void* d_out, int out_size)
{
    const float* x    = (const float*)d_in[0];
    const float* cosT = (const float*)d_in[1];
    const float* sinT = (const float*)d_in[2];
    // d_in[3] = mask (exact causal -1e9 triu) -> applied analytically
    const float* wq   = (const float*)d_in[4];
    const float* wk   = (const float*)d_in[5];
    const float* wv   = (const float*)d_in[6];
    const float* wo   = (const float*)d_in[7];
    const float* qw   = (const float*)d_in[8];
    const float* kw   = (const float*)d_in[9];
    float* out = (float*)d_out;

    float *q, *k, *v;
    cudaGetSymbolAddress((void**)&q, g_q);
    cudaGetSymbolAddress((void**)&k, g_k);
    cudaGetSymbolAddress((void**)&v, g_v);

    __nv_bfloat16 *xh, *xl, *wqh, *wql, *wkh, *wkl, *wvh, *wvl, *woh, *wol;
    __nv_bfloat16 *qbh, *qbl, *kbh, *kbl, *vbh, *vbl, *aoh, *aol;
    cudaGetSymbolAddress((void**)&xh,  g_xh);  cudaGetSymbolAddress((void**)&xl,  g_xl);
    cudaGetSymbolAddress((void**)&wqh, g_wqh); cudaGetSymbolAddress((void**)&wql, g_wql);
    cudaGetSymbolAddress((void**)&wkh, g_wkh); cudaGetSymbolAddress((void**)&wkl, g_wkl);
    cudaGetSymbolAddress((void**)&wvh, g_wvh); cudaGetSymbolAddress((void**)&wvl, g_wvl);
    cudaGetSymbolAddress((void**)&woh, g_woh); cudaGetSymbolAddress((void**)&wol, g_wol);
    cudaGetSymbolAddress((void**)&qbh, g_qbh); cudaGetSymbolAddress((void**)&qbl, g_qbl);
    cudaGetSymbolAddress((void**)&kbh, g_kbh); cudaGetSymbolAddress((void**)&kbl, g_kbl);
    cudaGetSymbolAddress((void**)&vbh, g_vbh); cudaGetSymbolAddress((void**)&vbl, g_vbl);
    cudaGetSymbolAddress((void**)&aoh, g_aoh); cudaGetSymbolAddress((void**)&aol, g_aol);

    // hi/lo conversions for GEMM operands
    cvt(x,  xh,  xl,  (size_t)Tn*HSn);
    cvt(wq, wqh, wql, (size_t)Hn*Dn*HSn);
    cvt(wk, wkh, wkl, (size_t)HKVn*Dn*HSn);
    cvt(wv, wvh, wvl, (size_t)HKVn*Dn*HSn);
    cvt(wo, woh, wol, (size_t)HSn*Hn*Dn);

    cudaFuncSetAttribute(gemm_hmma, cudaFuncAttributeMaxDynamicSharedMemorySize, HSMEM);

    // Q projection
    gemm_hmma<<<dim3((Hn*Dn)/128, Tn/128), 256, HSMEM>>>(
        xh, xl, wqh, wql, q, Tn, Hn*Dn, HSn, nullptr, nullptr, nullptr, 1<<30);
    // fused K+V projections (one launch, 256 CTAs)
    gemm_hmma<<<dim3(2*(HKVn*Dn)/128, Tn/128), 256, HSMEM>>>(
        xh, xl, wkh, wkl, k, Tn, HKVn*Dn, HSn, wvh, wvl, v, (HKVn*Dn)/128);

    // RMS QK-norm + RoPE -> bf16 hi/lo
    rmsrope<<<dim3(Tn, Hn+HKVn), 128>>>(q, k, cosT, sinT, qw, kw,
                                        qbh, qbl, kbh, kbl);
    // V -> bf16 hi/lo
    cvt(v, vbh, vbl, (size_t)Tn*HKVn*Dn);

    // causal flash attention (HMMA split-bf16)
    cudaFuncSetAttribute(flash_hmma, cudaFuncAttributeMaxDynamicSharedMemorySize, FSMEM);
    flash_hmma<<<dim3(Sn/128, Hn, Bn), 256, FSMEM>>>(
        qbh, qbl, kbh, kbl, vbh, vbl, aoh, aol);

    // output projection
    gemm_hmma<<<dim3(HSn/128, Tn/128), 256, HSMEM>>>(
        aoh, aol, woh, wol, out, Tn, HSn, Hn*Dn, nullptr, nullptr, nullptr, 1<<30);
}

// round 13
// speedup vs baseline: 4.7338x; 1.3447x over previous
#include <cuda_runtime.h>
#include <cuda_bf16.h>
#include <cuda_fp16.h>
#include <math.h>
#include <stdint.h>

// Problem constants
#define Bn   2
#define Sn   2048
#define HSn  2048
#define Hn   16
#define HKVn 4
#define Dn   128
#define Tn   (Bn*Sn)          // 4096 tokens

// -------------------- scratch (device globals; allocation-free) -----------
__device__ float g_q[(size_t)Tn * (Hn*Dn)];
__device__ float g_k[(size_t)Tn * (HKVn*Dn)];
__device__ float g_v[(size_t)Tn * (HKVn*Dn)];

// fp16 planes: activations split hi/lo, weights single
__device__ __half g_xh[(size_t)Tn*HSn],       g_xl[(size_t)Tn*HSn];
__device__ __half g_wq[(size_t)Hn*Dn*HSn];
__device__ __half g_wk[(size_t)HKVn*Dn*HSn];
__device__ __half g_wv[(size_t)HKVn*Dn*HSn];
__device__ __half g_wo[(size_t)HSn*Hn*Dn];
// post-norm/rope: Q split hi/lo, K single; V single
__device__ __half g_qbh[(size_t)Tn*Hn*Dn],    g_qbl[(size_t)Tn*Hn*Dn];
__device__ __half g_kb [(size_t)Tn*HKVn*Dn];
__device__ __half g_vb [(size_t)Tn*HKVn*Dn];
// attention output hi/lo (A operand of O-projection)
__device__ __half g_aoh[(size_t)Tn*Hn*Dn],    g_aol[(size_t)Tn*Hn*Dn];

// ======================= helpers ==========================================
__device__ __forceinline__ uint32_t smem_u32(const void* p) {
    uint32_t a;
    asm("{ .reg .u64 t; cvta.to.shared.u64 t, %1; cvt.u32.u64 %0, t; }"
        : "=r"(a) : "l"(p));
    return a;
}
__device__ __forceinline__ void cpasync16(uint32_t dst, const void* src) {
    asm volatile("cp.async.cg.shared.global [%0], [%1], 16;" :: "r"(dst), "l"(src));
}
#define CP_COMMIT() asm volatile("cp.async.commit_group;" ::: "memory")
__device__ __forceinline__ void ldsm4(uint32_t* r, uint32_t addr) {
    asm volatile("ldmatrix.sync.aligned.m8n8.x4.shared.b16 {%0,%1,%2,%3}, [%4];"
        : "=r"(r[0]), "=r"(r[1]), "=r"(r[2]), "=r"(r[3]) : "r"(addr));
}
__device__ __forceinline__ void ldsm4t(uint32_t* r, uint32_t addr) {
    asm volatile("ldmatrix.sync.aligned.m8n8.x4.trans.shared.b16 {%0,%1,%2,%3}, [%4];"
        : "=r"(r[0]), "=r"(r[1]), "=r"(r[2]), "=r"(r[3]) : "r"(addr));
}
__device__ __forceinline__ void mma_f16(float* d, const uint32_t* a, const uint32_t* b) {
    asm volatile("mma.sync.aligned.m16n8k16.row.col.f32.f16.f16.f32 "
                 "{%0,%1,%2,%3}, {%4,%5,%6,%7}, {%8,%9}, {%0,%1,%2,%3};"
                 : "+f"(d[0]), "+f"(d[1]), "+f"(d[2]), "+f"(d[3])
                 : "r"(a[0]), "r"(a[1]), "r"(a[2]), "r"(a[3]),
                   "r"(b[0]), "r"(b[1]));
}
__device__ __forceinline__ uint32_t packh(__half a, __half b) {
    return (uint32_t)__half_as_ushort(a) |
           ((uint32_t)__half_as_ushort(b) << 16);
}

// ==================== fp32 -> fp16 conversions ============================
__global__ __launch_bounds__(256) void cvt_hilo_h(const float* __restrict__ x,
                                                  __half* __restrict__ h,
                                                  __half* __restrict__ l,
                                                  int n4)
{
    int i = blockIdx.x*256 + threadIdx.x;
    if (i >= n4) return;
    float4 v = ((const float4*)x)[i];
    __half h0 = __float2half_rn(v.x);
    __half h1 = __float2half_rn(v.y);
    __half h2 = __float2half_rn(v.z);
    __half h3 = __float2half_rn(v.w);
    __half l0 = __float2half_rn(v.x - __half2float(h0));
    __half l1 = __float2half_rn(v.y - __half2float(h1));
    __half l2 = __float2half_rn(v.z - __half2float(h2));
    __half l3 = __float2half_rn(v.w - __half2float(h3));
    ((ushort4*)h)[i] = make_ushort4(__half_as_ushort(h0), __half_as_ushort(h1),
                                    __half_as_ushort(h2), __half_as_ushort(h3));
    ((ushort4*)l)[i] = make_ushort4(__half_as_ushort(l0), __half_as_ushort(l1),
                                    __half_as_ushort(l2), __half_as_ushort(l3));
}

__global__ __launch_bounds__(256) void cvt_h(const float* __restrict__ x,
                                             __half* __restrict__ h, int n4)
{
    int i = blockIdx.x*256 + threadIdx.x;
    if (i >= n4) return;
    float4 v = ((const float4*)x)[i];
    ((ushort4*)h)[i] = make_ushort4(
        __half_as_ushort(__float2half_rn(v.x)), __half_as_ushort(__float2half_rn(v.y)),
        __half_as_ushort(__float2half_rn(v.z)), __half_as_ushort(__float2half_rn(v.w)));
}

// ========== HMMA GEMM: C = A * B^T, A = Ah+Al (fp16), B single fp16 =======
// 128x128 tile, BK=32, 256 threads (8 warps 2x4), 3-stage cp.async pipeline.
#define HARR 5120                    // fp16 per array (128 rows * 40)
#define HSTG (3*HARR*2)              // bytes per stage (Ah, Al, B) = 30720
#define HSMEM (3*HSTG)               // 92160 B

__global__ __launch_bounds__(256, 1)
void gemm_hmma(const __half* __restrict__ Ah, const __half* __restrict__ Al,
               const __half* __restrict__ Bw,
               float* __restrict__ C, int M, int N, int K,
               const __half* Bw2, float* C2, int nx1)
{
    extern __shared__ __half smb[];
    const uint32_t sbase = smem_u32(smb);

    int bx = blockIdx.x;
    const __half* pB = Bw;
    float* pC = C;
    if (bx >= nx1) { bx -= nx1; pB = Bw2; pC = C2; }

    const int tid  = threadIdx.x;
    const int lane = tid & 31;
    const int wid  = tid >> 5;
    const int m0w  = (wid >> 2) * 64;
    const int n0w  = (wid & 3) * 32;
    const int mrow0 = blockIdx.y * 128;
    const int ncol0 = bx * 128;
    const int NC = K / 32;

    float acc[4][4][4];
    #pragma unroll
    for (int mt = 0; mt < 4; mt++)
        #pragma unroll
        for (int nt = 0; nt < 4; nt++)
            #pragma unroll
            for (int i = 0; i < 4; i++) acc[mt][nt][i] = 0.f;

    auto load_chunk = [&](int c, int st) {
        const int k0 = c * 32;
        const uint32_t b0 = sbase + (uint32_t)st * HSTG;
        #pragma unroll
        for (int i = 0; i < 2; i++) {
            int id  = i*256 + tid;
            int row = id >> 2;
            int cc  = id & 3;
            uint32_t d  = (uint32_t)(row*80 + cc*16);
            size_t   ga = (size_t)(mrow0 + row)*K + k0 + cc*8;
            size_t   gb = (size_t)(ncol0 + row)*K + k0 + cc*8;
            cpasync16(b0 + 0*HARR*2 + d, Ah + ga);
            cpasync16(b0 + 1*HARR*2 + d, Al + ga);
            cpasync16(b0 + 2*HARR*2 + d, pB + gb);
        }
        CP_COMMIT();
    };

    load_chunk(0, 0);
    load_chunk(1, 1);

    for (int c = 0; c < NC; c++) {
        if (c + 1 < NC) asm volatile("cp.async.wait_group 1;" ::: "memory");
        else            asm volatile("cp.async.wait_group 0;" ::: "memory");
        __syncthreads();
        if (c + 2 < NC) load_chunk(c + 2, (c + 2) % 3);

        const uint32_t b0  = sbase + (uint32_t)(c % 3) * HSTG;
        const uint32_t aHi = b0 + 0*HARR*2;
        const uint32_t aLo = b0 + 1*HARR*2;
        const uint32_t bB  = b0 + 2*HARR*2;

        #pragma unroll
        for (int ks = 0; ks < 2; ks++) {
            uint32_t ah[4][4], al[4][4], bf[2][4];
            const uint32_t aoff = (uint32_t)(ks*32 + (lane >> 4)*16);
            const uint32_t boff = (uint32_t)(ks*32 + ((lane >> 3) & 1)*16);
            #pragma unroll
            for (int mt = 0; mt < 4; mt++) {
                uint32_t r = (uint32_t)((m0w + mt*16 + (lane & 15)) * 80) + aoff;
                ldsm4(ah[mt], aHi + r);
                ldsm4(al[mt], aLo + r);
            }
            #pragma unroll
            for (int n2 = 0; n2 < 2; n2++) {
                uint32_t r = (uint32_t)((n0w + n2*16 + ((lane>>4)<<3) + (lane & 7)) * 80) + boff;
                ldsm4(bf[n2], bB + r);
            }
            #pragma unroll
            for (int mt = 0; mt < 4; mt++)
                #pragma unroll
                for (int nt = 0; nt < 4; nt++)
                    mma_f16(acc[mt][nt], ah[mt], &bf[nt>>1][(nt&1)*2]);
            #pragma unroll
            for (int mt = 0; mt < 4; mt++)
                #pragma unroll
                for (int nt = 0; nt < 4; nt++)
                    mma_f16(acc[mt][nt], al[mt], &bf[nt>>1][(nt&1)*2]);
        }
        __syncthreads();
    }

    #pragma unroll
    for (int mt = 0; mt < 4; mt++)
        #pragma unroll
        for (int nt = 0; nt < 4; nt++) {
            const float* d = acc[mt][nt];
            int row = mrow0 + m0w + mt*16 + (lane >> 2);
            int col = ncol0 + n0w + nt*8 + (lane & 3)*2;
            *(float2*)(pC + (size_t)row*N + col)     = make_float2(d[0], d[1]);
            *(float2*)(pC + (size_t)(row+8)*N + col) = make_float2(d[2], d[3]);
        }
}

// ===== fused per-head RMSNorm + RoPE -> fp16 (Q hi/lo, K single) ==========
__global__ __launch_bounds__(128) void rmsrope(const float* __restrict__ q,
                                               const float* __restrict__ k,
                                               const float* __restrict__ cosT,
                                               const float* __restrict__ sinT,
                                               const float* __restrict__ qw,
                                               const float* __restrict__ kw,
                                               __half* __restrict__ qh,
                                               __half* __restrict__ ql,
                                               __half* __restrict__ kh)
{
    const int t = blockIdx.x;
    const int h = blockIdx.y;
    const int d = threadIdx.x;
    const bool isq = (h < Hn);
    const float* base = isq ? (q + (size_t)t*(Hn*Dn) + h*Dn)
                            : (k + (size_t)t*(HKVn*Dn) + (h-Hn)*Dn);
    const float* w = isq ? qw : kw;

    float v = base[d];
    float ss = v*v;
    #pragma unroll
    for (int o = 16; o; o >>= 1) ss += __shfl_xor_sync(0xffffffffu, ss, o);
    __shared__ float red[4];
    if ((d & 31) == 0) red[d >> 5] = ss;
    __syncthreads();
    float tot = red[0] + red[1] + red[2] + red[3];
    float inv = rsqrtf(tot * (1.0f/128.0f) + 1e-6f);
    float nv = v * inv * w[d];

    __shared__ float sh[128];
    sh[d] = nv;
    __syncthreads();
    float rot = (d < 64) ? -sh[d+64] : sh[d-64];
    const int s = t & (Sn-1);
    float r = nv * cosT[(size_t)s*Dn + d] + rot * sinT[(size_t)s*Dn + d];

    __half hi = __float2half_rn(r);
    if (isq) {
        size_t o1 = ((size_t)t*Hn + h)*Dn + d;
        qh[o1] = hi;
        ql[o1] = __float2half_rn(r - __half2float(hi));
    } else {
        size_t o1 = ((size_t)t*HKVn + (h-Hn))*Dn + d;
        kh[o1] = hi;
    }
}

// ============== causal flash attention (HMMA fp16, 2-term) ================
// grid (16 qtiles, 16 heads, 2 batch), 256 threads, BQ=128, BKV=64, D=128.
#define FSTR 272                 // bytes per smem row (128 fp16 + 8 pad)
#define FQ_BYTES (128*FSTR)      // 34816
#define FKV_BYTES (64*FSTR)      // 17408
#define FSTAGE (2*FKV_BYTES)     // K, V = 34816
#define FSMEM (2*FQ_BYTES + 2*FSTAGE)  // 139264

__global__ __launch_bounds__(256, 1)
void flash_hmma(const __half* __restrict__ qh, const __half* __restrict__ qlp,
                const __half* __restrict__ kp, const __half* __restrict__ vp,
                __half* __restrict__ oh, __half* __restrict__ olp)
{
    extern __shared__ char smc[];
    const uint32_t sb = smem_u32(smc);
    const uint32_t Qh = sb, Ql = sb + FQ_BYTES;

    const int qt = gridDim.x - 1 - blockIdx.x;   // heavy tiles first
    const int h = blockIdx.y, b = blockIdx.z;
    const int kvh = h >> 2;
    const int tid = threadIdx.x, lane = tid & 31, w = tid >> 5;
    const float scale = 0.08838834764831845f;

    // Q tile (hi+lo): 128 rows x 16 chunks, hi AND lo per id
    #pragma unroll
    for (int i = 0; i < 8; i++) {
        int id = i*256 + tid;
        int row = id >> 4, ch = id & 15;
        size_t g = ((size_t)(b*Sn + qt*128 + row)*Hn + h)*Dn + ch*8;
        uint32_t d = (uint32_t)(row*FSTR + ch*16);
        cpasync16(Qh + d, qh  + g);
        cpasync16(Ql + d, qlp + g);
    }
    CP_COMMIT();

    auto load_kv = [&](int kt, int st) {
        uint32_t base = sb + 2*FQ_BYTES + (uint32_t)st * FSTAGE;
        #pragma unroll
        for (int i = 0; i < 4; i++) {
            int id = i*256 + tid;
            int row = id >> 4, ch = id & 15;
            size_t g = ((size_t)(b*Sn + kt*64 + row)*HKVn + kvh)*Dn + ch*8;
            uint32_t d = (uint32_t)(row*FSTR + ch*16);
            cpasync16(base + 0*FKV_BYTES + d, kp + g);
            cpasync16(base + 1*FKV_BYTES + d, vp + g);
        }
        CP_COMMIT();
    };

    const int nkv = 2*qt + 2;
    load_kv(0, 0);

    float oacc[16][4];
    #pragma unroll
    for (int i = 0; i < 16; i++)
        #pragma unroll
        for (int j = 0; j < 4; j++) oacc[i][j] = 0.f;
    float m0 = -1e30f, m1 = -1e30f, l0 = 0.f, l1 = 0.f;
    const int gr0 = qt*128 + w*16 + (lane >> 2);
    const int gr1 = gr0 + 8;

    for (int kt = 0; kt < nkv; kt++) {
        asm volatile("cp.async.wait_group 0;" ::: "memory");
        __syncthreads();
        if (kt + 1 < nkv) load_kv(kt + 1, (kt + 1) & 1);

        const uint32_t kb = sb + 2*FQ_BYTES + (uint32_t)(kt & 1) * FSTAGE;

        // ---- S = Q K^T (Qh·K + Ql·K) ----
        float sacc[8][4];
        #pragma unroll
        for (int i = 0; i < 8; i++)
            #pragma unroll
            for (int j = 0; j < 4; j++) sacc[i][j] = 0.f;

        #pragma unroll
        for (int ks = 0; ks < 8; ks++) {
            uint32_t qhf[4], qlf[4], khf[4][4];
            const uint32_t aoff = (uint32_t)(ks*32 + (lane >> 4)*16);
            const uint32_t arow = (uint32_t)((w*16 + (lane & 15)) * FSTR);
            ldsm4(qhf, Qh + arow + aoff);
            ldsm4(qlf, Ql + arow + aoff);
            const uint32_t boff = (uint32_t)(ks*32 + ((lane >> 3) & 1)*16);
            #pragma unroll
            for (int n2 = 0; n2 < 4; n2++) {
                uint32_t r = (uint32_t)((n2*16 + ((lane>>4)<<3) + (lane & 7)) * FSTR) + boff;
                ldsm4(khf[n2], kb + r);
            }
            #pragma unroll
            for (int nt = 0; nt < 8; nt++)
                mma_f16(sacc[nt], qhf, &khf[nt>>1][(nt&1)*2]);
            #pragma unroll
            for (int nt = 0; nt < 8; nt++)
                mma_f16(sacc[nt], qlf, &khf[nt>>1][(nt&1)*2]);
        }

        // ---- softmax (online) ----
        const bool dz = (kt >= 2*qt);
        float mx0 = -1e30f, mx1 = -1e30f;
        #pragma unroll
        for (int nt = 0; nt < 8; nt++) {
            const int gc = kt*64 + nt*8 + (lane & 3)*2;
            float s0 = sacc[nt][0]*scale, s1 = sacc[nt][1]*scale;
            float s2 = sacc[nt][2]*scale, s3 = sacc[nt][3]*scale;
            if (dz) {
                if (gc     > gr0) s0 = -1e30f;
                if (gc + 1 > gr0) s1 = -1e30f;
                if (gc     > gr1) s2 = -1e30f;
                if (gc + 1 > gr1) s3 = -1e30f;
            }
            sacc[nt][0] = s0; sacc[nt][1] = s1; sacc[nt][2] = s2; sacc[nt][3] = s3;
            mx0 = fmaxf(mx0, fmaxf(s0, s1));
            mx1 = fmaxf(mx1, fmaxf(s2, s3));
        }
        mx0 = fmaxf(mx0, __shfl_xor_sync(0xffffffffu, mx0, 1));
        mx0 = fmaxf(mx0, __shfl_xor_sync(0xffffffffu, mx0, 2));
        mx1 = fmaxf(mx1, __shfl_xor_sync(0xffffffffu, mx1, 1));
        mx1 = fmaxf(mx1, __shfl_xor_sync(0xffffffffu, mx1, 2));
        const float mn0 = fmaxf(m0, mx0), mn1 = fmaxf(m1, mx1);
        const float cr0 = __expf(m0 - mn0), cr1 = __expf(m1 - mn1);
        m0 = mn0; m1 = mn1;

        uint32_t pha[8], phb[8], pla[8], plb[8];
        float sum0 = 0.f, sum1 = 0.f;
        #pragma unroll
        for (int nt = 0; nt < 8; nt++) {
            float p0 = __expf(sacc[nt][0] - mn0);
            float p1 = __expf(sacc[nt][1] - mn0);
            float p2 = __expf(sacc[nt][2] - mn1);
            float p3 = __expf(sacc[nt][3] - mn1);
            sum0 += p0 + p1; sum1 += p2 + p3;
            __half h0 = __float2half_rn(p0);
            __half h1 = __float2half_rn(p1);
            __half h2 = __float2half_rn(p2);
            __half h3 = __float2half_rn(p3);
            pha[nt] = packh(h0, h1);
            phb[nt] = packh(h2, h3);
            pla[nt] = packh(__float2half_rn(p0 - __half2float(h0)),
                            __float2half_rn(p1 - __half2float(h1)));
            plb[nt] = packh(__float2half_rn(p2 - __half2float(h2)),
                            __float2half_rn(p3 - __half2float(h3)));
        }
        sum0 += __shfl_xor_sync(0xffffffffu, sum0, 1);
        sum0 += __shfl_xor_sync(0xffffffffu, sum0, 2);
        sum1 += __shfl_xor_sync(0xffffffffu, sum1, 1);
        sum1 += __shfl_xor_sync(0xffffffffu, sum1, 2);
        l0 = l0*cr0 + sum0;
        l1 = l1*cr1 + sum1;
        #pragma unroll
        for (int nt = 0; nt < 16; nt++) {
            oacc[nt][0] *= cr0; oacc[nt][1] *= cr0;
            oacc[nt][2] *= cr1; oacc[nt][3] *= cr1;
        }

        // ---- O += P V (Ph·V + Pl·V), V via ldmatrix.trans ----
        #pragma unroll
        for (int ks = 0; ks < 4; ks++) {
            uint32_t ah4[4] = { pha[2*ks], phb[2*ks], pha[2*ks+1], phb[2*ks+1] };
            uint32_t al4[4] = { pla[2*ks], plb[2*ks], pla[2*ks+1], plb[2*ks+1] };
            const uint32_t vrow = (uint32_t)((ks*16 + ((lane>>3)&1)*8 + (lane&7)) * FSTR);
            #pragma unroll
            for (int half = 0; half < 2; half++) {
                uint32_t vhf[4][4];
                #pragma unroll
                for (int n2 = 0; n2 < 4; n2++) {
                    uint32_t coff = (uint32_t)(((half*4 + n2)*2 + (lane>>4)) * 16);
                    ldsm4t(vhf[n2], kb + 1*FKV_BYTES + vrow + coff);
                }
                #pragma unroll
                for (int nt = 0; nt < 8; nt++)
                    mma_f16(oacc[half*8 + nt], ah4, &vhf[nt>>1][(nt&1)*2]);
                #pragma unroll
                for (int nt = 0; nt < 8; nt++)
                    mma_f16(oacc[half*8 + nt], al4, &vhf[nt>>1][(nt&1)*2]);
            }
        }
    }

    // epilogue: normalize and emit hi/lo fp16
    const float inv0 = 1.f / l0, inv1 = 1.f / l1;
    const size_t t0 = (size_t)(b*Sn + qt*128 + w*16 + (lane >> 2));
    const size_t r0base = (t0*Hn + h)*Dn;
    const size_t r1base = ((t0 + 8)*Hn + h)*Dn;
    #pragma unroll
    for (int nt = 0; nt < 16; nt++) {
        const int col = nt*8 + (lane & 3)*2;
        float o0 = oacc[nt][0]*inv0, o1 = oacc[nt][1]*inv0;
        float o2 = oacc[nt][2]*inv1, o3 = oacc[nt][3]*inv1;
        __half h0 = __float2half_rn(o0), h1 = __float2half_rn(o1);
        __half h2 = __float2half_rn(o2), h3 = __float2half_rn(o3);
        *(uint32_t*)(oh  + r0base + col) = packh(h0, h1);
        *(uint32_t*)(oh  + r1base + col) = packh(h2, h3);
        *(uint32_t*)(olp + r0base + col) =
            packh(__float2half_rn(o0 - __half2float(h0)),
                  __float2half_rn(o1 - __half2float(h1)));
        *(uint32_t*)(olp + r1base + col) =
            packh(__float2half_rn(o2 - __half2float(h2)),
                  __float2half_rn(o3 - __half2float(h3)));
    }
}

// ==================== launch =============================================
extern "C" void kernel_launch(void* const* d_in, const int* in_sizes, int n_in,
                              void* d_out, int out_size)
{
    const float* x    = (const float*)d_in[0];
    const float* cosT = (const float*)d_in[1];
    const float* sinT = (const float*)d_in[2];
    // d_in[3] = mask (exact causal -1e9 triu) -> applied analytically
    const float* wq   = (const float*)d_in[4];
    const float* wk   = (const float*)d_in[5];
    const float* wv   = (const float*)d_in[6];
    const float* wo   = (const float*)d_in[7];
    const float* qw   = (const float*)d_in[8];
    const float* kw   = (const float*)d_in[9];
    float* out = (float*)d_out;

    float *q, *k, *v;
    cudaGetSymbolAddress((void**)&q, g_q);
    cudaGetSymbolAddress((void**)&k, g_k);
    cudaGetSymbolAddress((void**)&v, g_v);

    __half *xh, *xl, *wqp, *wkp, *wvp, *wop;
    __half *qbh, *qbl, *kb, *vb, *aoh, *aol;
    cudaGetSymbolAddress((void**)&xh,  g_xh);  cudaGetSymbolAddress((void**)&xl, g_xl);
    cudaGetSymbolAddress((void**)&wqp, g_wq);
    cudaGetSymbolAddress((void**)&wkp, g_wk);
    cudaGetSymbolAddress((void**)&wvp, g_wv);
    cudaGetSymbolAddress((void**)&wop, g_wo);
    cudaGetSymbolAddress((void**)&qbh, g_qbh); cudaGetSymbolAddress((void**)&qbl, g_qbl);
    cudaGetSymbolAddress((void**)&kb,  g_kb);
    cudaGetSymbolAddress((void**)&vb,  g_vb);
    cudaGetSymbolAddress((void**)&aoh, g_aoh); cudaGetSymbolAddress((void**)&aol, g_aol);

    // conversions: x -> fp16 hi/lo; weights -> fp16 single
    {
        int n4;
        n4 = (int)(((size_t)Tn*HSn)/4);
        cvt_hilo_h<<<(n4+255)/256, 256>>>(x, xh, xl, n4);
        n4 = (int)(((size_t)Hn*Dn*HSn)/4);
        cvt_h<<<(n4+255)/256, 256>>>(wq, wqp, n4);
        n4 = (int)(((size_t)HKVn*Dn*HSn)/4);
        cvt_h<<<(n4+255)/256, 256>>>(wk, wkp, n4);
        cvt_h<<<(n4+255)/256, 256>>>(wv, wvp, n4);
        n4 = (int)(((size_t)HSn*Hn*Dn)/4);
        cvt_h<<<(n4+255)/256, 256>>>(wo, wop, n4);
    }

    cudaFuncSetAttribute(gemm_hmma, cudaFuncAttributeMaxDynamicSharedMemorySize, HSMEM);

    // Q projection
    gemm_hmma<<<dim3((Hn*Dn)/128, Tn/128), 256, HSMEM>>>(
        xh, xl, wqp, q, Tn, Hn*Dn, HSn, nullptr, nullptr, 1<<30);
    // fused K+V projections
    gemm_hmma<<<dim3(2*(HKVn*Dn)/128, Tn/128), 256, HSMEM>>>(
        xh, xl, wkp, k, Tn, HKVn*Dn, HSn, wvp, v, (HKVn*Dn)/128);

    // RMS QK-norm + RoPE -> fp16 (Q hi/lo, K single)
    rmsrope<<<dim3(Tn, Hn+HKVn), 128>>>(q, k, cosT, sinT, qw, kw, qbh, qbl, kb);
    // V -> fp16 single
    {
        int n4 = (int)(((size_t)Tn*HKVn*Dn)/4);
        cvt_h<<<(n4+255)/256, 256>>>(v, vb, n4);
    }

    // causal flash attention (fp16 2-term)
    cudaFuncSetAttribute(flash_hmma, cudaFuncAttributeMaxDynamicSharedMemorySize, FSMEM);
    flash_hmma<<<dim3(Sn/128, Hn, Bn), 256, FSMEM>>>(qbh, qbl, kb, vb, aoh, aol);

    // output projection
    gemm_hmma<<<dim3(HSn/128, Tn/128), 256, HSMEM>>>(
        aoh, aol, wop, out, Tn, HSn, Hn*Dn, nullptr, nullptr, 1<<30);
}